// round 10
// baseline (speedup 1.0000x reference)
#include <cuda_runtime.h>
#include <cuda_fp16.h>
#include <math.h>
#include <mma.h>
using namespace nvcuda;

#define NN      20000
#define EE      320000
#define ETOT    (EE + NN)
#define IN_DIM  128
#define HID     256
#define HEADS   4
#define OUT_DIM 128
#define PADROWS 128

// ------------------- scratch -------------------
__device__ float  g_h1 [(size_t)(NN + PADROWS) * HID];
__device__ __half g_h1h[(size_t)(NN + PADROWS) * HID];
__device__ float  g_out1[(size_t)(NN + PADROWS) * HID];
__device__ __half g_h2h[(size_t)(NN + PADROWS) * OUT_DIM];
__device__ float  g_out2[(size_t)NN * OUT_DIM];

__device__ int g_srcA[ETOT], g_dstA[ETOT];
__device__ int g_cnt[NN];                    // zero at load; re-zeroed by k_apply2 tail
__device__ int g_off[NN + 1];
__device__ int g_pos[NN];
__device__ int g_csr[ETOT];

__device__ float g_as1[NN * HEADS], g_ad1[NN * HEADS];
__device__ float g_as2[NN], g_ad2[NN];
__device__ float g_sum[HID], g_sqs[HID];

__device__ __forceinline__ float lrelu(float v) { return v > 0.f ? v : 0.2f * v; }

// ------------------- decode + count (+detect, +zero BN accums) -------------------
__global__ void k_decode(const void* __restrict__ ei) {
    __shared__ int sh_is64;
    if (threadIdx.x == 0) {
        const unsigned long long* p = (const unsigned long long*)ei;
        int is64 = 1;
        for (int k = 0; k < 16; k++)
            if (p[k] >= (unsigned long long)NN) { is64 = 0; break; }
        sh_is64 = is64;
    }
    __syncthreads();
    int e = blockIdx.x * 256 + threadIdx.x;
    if (e < HID) { g_sum[e] = 0.f; g_sqs[e] = 0.f; }
    if (e >= ETOT) return;
    int s, d;
    if (e >= EE) { s = e - EE; d = e - EE; }
    else if (sh_is64) {
        const long long* p = (const long long*)ei;
        s = (int)p[e]; d = (int)p[EE + e];
    } else {
        const int* p = (const int*)ei;
        s = p[e]; d = p[EE + e];
    }
    g_srcA[e] = s; g_dstA[e] = d;
    atomicAdd(&g_cnt[d], 1);
}

// ------------------- coalesced scan -------------------
__global__ void k_scan() {
    __shared__ int wtot[8];
    int tid = threadIdx.x, lane = tid & 31, wid = tid >> 5;
    const int WCH = NN / 8;
    const int IT  = (WCH + 31) / 32;
    int base = wid * WCH;
    int tot = 0;
    for (int j = 0; j < IT; j++) {
        int o = j * 32 + lane;
        if (o < WCH) tot += g_cnt[base + o];
    }
    #pragma unroll
    for (int o = 16; o; o >>= 1) tot += __shfl_xor_sync(0xffffffffu, tot, o);
    if (lane == 0) wtot[wid] = tot;
    __syncthreads();
    if (tid == 0) {
        int run = 0;
        #pragma unroll
        for (int w = 0; w < 8; w++) { int t = wtot[w]; wtot[w] = run; run += t; }
        g_off[NN] = run;
    }
    __syncthreads();
    int run = wtot[wid];
    for (int j = 0; j < IT; j++) {
        int o = j * 32 + lane;
        int v = (o < WCH) ? g_cnt[base + o] : 0;
        int incl = v;
        #pragma unroll
        for (int s = 1; s < 32; s <<= 1) {
            int t = __shfl_up_sync(0xffffffffu, incl, s);
            if (lane >= s) incl += t;
        }
        if (o < WCH) {
            int off = run + incl - v;
            g_off[base + o] = off;
            g_pos[base + o] = off;
        }
        run += __shfl_sync(0xffffffffu, incl, 31);
    }
}

__global__ void k_fill() {
    int e = blockIdx.x * blockDim.x + threadIdx.x;
    if (e >= ETOT) return;
    int p = atomicAdd(&g_pos[g_dstA[e]], 1);
    g_csr[p] = g_srcA[e];
}

// ------------------- 3xTF32 wmma GEMM with fused epilogues -------------------
// smem: As 128x40 (5120 f) + Bs 32x72 (2304 f) live in main loop;
// Cs 128x68 (8704 f) reuses the same buffer in the epilogue.
__device__ __forceinline__ void wgemm_core(const float* __restrict__ A,
                                           const float* __restrict__ B,
                                           int M, int K, int Nc,
                                           int m0, int n0, bool guardA,
                                           float* smem_buf) {
    float (*As)[40] = (float(*)[40])smem_buf;
    float (*Bs)[72] = (float(*)[72])(smem_buf + 5120);
    float (*Cs)[68] = (float(*)[68])smem_buf;
    int tid = threadIdx.x;
    int w  = tid >> 5;
    int wm = w >> 1, wn = w & 1;

    wmma::fragment<wmma::accumulator, 16, 16, 8, float> acc[2][2];
    #pragma unroll
    for (int r = 0; r < 2; r++)
        #pragma unroll
        for (int c = 0; c < 2; c++) wmma::fill_fragment(acc[r][c], 0.f);

    for (int k0 = 0; k0 < K; k0 += 32) {
        #pragma unroll
        for (int i = 0; i < 4; i++) {
            int idx = tid + i * 256;
            int r = idx >> 3, c4 = (idx & 7) * 4;
            float4 v;
            if (!guardA || (m0 + r) < M)
                v = *(const float4*)&A[(size_t)(m0 + r) * K + k0 + c4];
            else
                v = make_float4(0.f, 0.f, 0.f, 0.f);
            *(float4*)&As[r][c4] = v;
        }
        #pragma unroll
        for (int i = 0; i < 2; i++) {
            int idx = tid + i * 256;
            int r = idx >> 4, c4 = (idx & 15) * 4;
            *(float4*)&Bs[r][c4] = *(const float4*)&B[(size_t)(k0 + r) * Nc + n0 + c4];
        }
        __syncthreads();
        #pragma unroll
        for (int kk = 0; kk < 32; kk += 8) {
            wmma::fragment<wmma::matrix_a, 16, 16, 8, wmma::precision::tf32, wmma::row_major> ahi[2], alo[2];
            wmma::fragment<wmma::matrix_b, 16, 16, 8, wmma::precision::tf32, wmma::row_major> bhi[2], blo[2];
            #pragma unroll
            for (int r = 0; r < 2; r++) {
                wmma::load_matrix_sync(ahi[r], &As[wm * 32 + r * 16][kk], 40);
                #pragma unroll
                for (int t = 0; t < ahi[r].num_elements; t++) {
                    float v = ahi[r].x[t];
                    float h = wmma::__float_to_tf32(v);
                    ahi[r].x[t] = h;
                    alo[r].x[t] = wmma::__float_to_tf32(v - h);
                }
            }
            #pragma unroll
            for (int c = 0; c < 2; c++) {
                wmma::load_matrix_sync(bhi[c], &Bs[kk][wn * 32 + c * 16], 72);
                #pragma unroll
                for (int t = 0; t < bhi[c].num_elements; t++) {
                    float v = bhi[c].x[t];
                    float h = wmma::__float_to_tf32(v);
                    bhi[c].x[t] = h;
                    blo[c].x[t] = wmma::__float_to_tf32(v - h);
                }
            }
            #pragma unroll
            for (int r = 0; r < 2; r++)
                #pragma unroll
                for (int c = 0; c < 2; c++) {
                    wmma::mma_sync(acc[r][c], ahi[r], blo[c], acc[r][c]);
                    wmma::mma_sync(acc[r][c], alo[r], bhi[c], acc[r][c]);
                    wmma::mma_sync(acc[r][c], ahi[r], bhi[c], acc[r][c]);
                }
        }
        __syncthreads();
    }
    // stage C in smem
    #pragma unroll
    for (int r = 0; r < 2; r++)
        #pragma unroll
        for (int c = 0; c < 2; c++)
            wmma::store_matrix_sync(&Cs[wm * 32 + r * 16][wn * 32 + c * 16], acc[r][c], 68, wmma::mem_row_major);
    __syncthreads();
}

// gemm1: C -> g_h1 (fp32) + g_h1h (half); alpha1 for head = blockIdx.x
__global__ void k_gemm1(const float* __restrict__ x, const float* __restrict__ W1,
                        const float* __restrict__ asrc, const float* __restrict__ adst) {
    __shared__ __align__(16) float smem_buf[8704];
    int m0 = blockIdx.y * 128, n0 = blockIdx.x * 64;
    wgemm_core(x, W1, NN, IN_DIM, HID, m0, n0, true, smem_buf);
    float (*Cs)[68] = (float(*)[68])smem_buf;
    int tid = threadIdx.x, lane = tid & 31, w = tid >> 5;

    #pragma unroll
    for (int i = 0; i < 8; i++) {
        int idx = tid + i * 256;
        int r = idx >> 4, c4 = (idx & 15) * 4;
        float4 v = *(const float4*)&Cs[r][c4];
        *(float4*)&g_h1[(size_t)(m0 + r) * HID + n0 + c4] = v;
        __half2 p0 = __floats2half2_rn(v.x, v.y);
        __half2 p1 = __floats2half2_rn(v.z, v.w);
        uint2 raw;
        raw.x = *(unsigned*)&p0; raw.y = *(unsigned*)&p1;
        *(uint2*)&g_h1h[(size_t)(m0 + r) * HID + n0 + c4] = raw;
    }
    // alpha for this head (block covers exactly one head's 64 channels)
    int h = blockIdx.x;
    float as0 = asrc[h * 64 + lane * 2], as1 = asrc[h * 64 + lane * 2 + 1];
    float ad0 = adst[h * 64 + lane * 2], ad1 = adst[h * 64 + lane * 2 + 1];
    #pragma unroll
    for (int rr = 0; rr < 16; rr++) {
        int row = w * 16 + rr;
        float2 v = *(const float2*)&Cs[row][lane * 2];
        float vs = v.x * as0 + v.y * as1;
        float vd = v.x * ad0 + v.y * ad1;
        #pragma unroll
        for (int o = 16; o; o >>= 1) {
            vs += __shfl_down_sync(0xffffffffu, vs, o);
            vd += __shfl_down_sync(0xffffffffu, vd, o);
        }
        int gr = m0 + row;
        if (lane == 0 && gr < NN) {
            g_as1[gr * 4 + h] = vs;
            g_ad1[gr * 4 + h] = vd;
        }
    }
}

// gemm2: A = g_out1 (post BN+ELU), C -> g_h2h (half only); partial alpha2 via atomics;
// block (0,0) zeroes BN accums for layer 2.
__global__ void k_gemm2(const float* __restrict__ W2,
                        const float* __restrict__ asrc, const float* __restrict__ adst) {
    __shared__ __align__(16) float smem_buf[8704];
    if (blockIdx.x == 0 && blockIdx.y == 0 && threadIdx.x < HID) {
        g_sum[threadIdx.x] = 0.f; g_sqs[threadIdx.x] = 0.f;
    }
    int m0 = blockIdx.y * 128, n0 = blockIdx.x * 64;
    wgemm_core(g_out1, W2, NN, HID, OUT_DIM, m0, n0, false, smem_buf);
    float (*Cs)[68] = (float(*)[68])smem_buf;
    int tid = threadIdx.x, lane = tid & 31, w = tid >> 5;

    #pragma unroll
    for (int i = 0; i < 8; i++) {
        int idx = tid + i * 256;
        int r = idx >> 4, c4 = (idx & 15) * 4;
        float4 v = *(const float4*)&Cs[r][c4];
        __half2 p0 = __floats2half2_rn(v.x, v.y);
        __half2 p1 = __floats2half2_rn(v.z, v.w);
        uint2 raw;
        raw.x = *(unsigned*)&p0; raw.y = *(unsigned*)&p1;
        *(uint2*)&g_h2h[(size_t)(m0 + r) * OUT_DIM + n0 + c4] = raw;
    }
    float as0 = asrc[n0 + lane * 2], as1 = asrc[n0 + lane * 2 + 1];
    float ad0 = adst[n0 + lane * 2], ad1 = adst[n0 + lane * 2 + 1];
    #pragma unroll
    for (int rr = 0; rr < 16; rr++) {
        int row = w * 16 + rr;
        float2 v = *(const float2*)&Cs[row][lane * 2];
        float vs = v.x * as0 + v.y * as1;
        float vd = v.x * ad0 + v.y * ad1;
        #pragma unroll
        for (int o = 16; o; o >>= 1) {
            vs += __shfl_down_sync(0xffffffffu, vs, o);
            vd += __shfl_down_sync(0xffffffffu, vd, o);
        }
        int gr = m0 + row;
        if (lane == 0 && gr < NN) {
            atomicAdd(&g_as2[gr], vs);
            atomicAdd(&g_ad2[gr], vd);
        }
    }
}

// ------------------- layer-1 softmax+gather: 2 warps/node, fp16 gather -------------------
__global__ void k_agg1() {
    int gwarp = (blockIdx.x * blockDim.x + threadIdx.x) >> 5;
    int lane = threadIdx.x & 31;
    int node = gwarp >> 1, half = gwarp & 1;
    if (node >= NN) return;
    int beg = g_off[node], end = g_off[node + 1];
    float4 adv = *(const float4*)(g_ad1 + node * 4);

    float m0 = -1e30f, m1 = -1e30f, m2 = -1e30f, m3 = -1e30f;
    float d0 = 0.f, d1 = 0.f, d2 = 0.f, d3 = 0.f;
    for (int i = beg + lane; i < end; i += 32) {
        int s = g_csr[i];
        float4 a = *(const float4*)(g_as1 + s * 4);
        float v0 = lrelu(a.x + adv.x), v1 = lrelu(a.y + adv.y);
        float v2 = lrelu(a.z + adv.z), v3 = lrelu(a.w + adv.w);
        float n0 = fmaxf(m0, v0); d0 = d0 * __expf(m0 - n0) + __expf(v0 - n0); m0 = n0;
        float n1 = fmaxf(m1, v1); d1 = d1 * __expf(m1 - n1) + __expf(v1 - n1); m1 = n1;
        float n2 = fmaxf(m2, v2); d2 = d2 * __expf(m2 - n2) + __expf(v2 - n2); m2 = n2;
        float n3 = fmaxf(m3, v3); d3 = d3 * __expf(m3 - n3) + __expf(v3 - n3); m3 = n3;
    }
    #pragma unroll
    for (int o = 16; o; o >>= 1) {
        float mo, dd, mn;
        mo = __shfl_xor_sync(0xffffffffu, m0, o); dd = __shfl_xor_sync(0xffffffffu, d0, o);
        mn = fmaxf(m0, mo); d0 = d0 * __expf(m0 - mn) + dd * __expf(mo - mn); m0 = mn;
        mo = __shfl_xor_sync(0xffffffffu, m1, o); dd = __shfl_xor_sync(0xffffffffu, d1, o);
        mn = fmaxf(m1, mo); d1 = d1 * __expf(m1 - mn) + dd * __expf(mo - mn); m1 = mn;
        mo = __shfl_xor_sync(0xffffffffu, m2, o); dd = __shfl_xor_sync(0xffffffffu, d2, o);
        mn = fmaxf(m2, mo); d2 = d2 * __expf(m2 - mn) + dd * __expf(mo - mn); m2 = mn;
        mo = __shfl_xor_sync(0xffffffffu, m3, o); dd = __shfl_xor_sync(0xffffffffu, d3, o);
        mn = fmaxf(m3, mo); d3 = d3 * __expf(m3 - mn) + dd * __expf(mo - mn); m3 = mn;
    }

    int hsel = half * 2 + (lane >> 4);
    float ad_l  = hsel == 0 ? adv.x : hsel == 1 ? adv.y : hsel == 2 ? adv.z : adv.w;
    float m_l   = hsel == 0 ? m0 : hsel == 1 ? m1 : hsel == 2 ? m2 : m3;
    float den_l = hsel == 0 ? d0 : hsel == 1 ? d1 : hsel == 2 ? d2 : d3;
    float inv_l = 1.f / (den_l + 1e-16f);

    float4 acc = make_float4(0.f, 0.f, 0.f, 0.f);
    const uint2* __restrict__ h1h = (const uint2*)g_h1h;
    int fo = half * 32 + lane;                 // uint2 index within 64-uint2 row
    for (int i = beg; i < end; i++) {
        int s = g_csr[i];
        float a = g_as1[(s << 2) + hsel];
        float c = __expf(lrelu(a + ad_l) - m_l) * inv_l;
        uint2 raw = h1h[(size_t)s * 64 + fo];
        float2 f0 = __half22float2(*(__half2*)&raw.x);
        float2 f1 = __half22float2(*(__half2*)&raw.y);
        acc.x += f0.x * c; acc.y += f0.y * c; acc.z += f1.x * c; acc.w += f1.y * c;
    }
    ((float4*)(g_out1 + (size_t)node * HID))[fo] = acc;
}

// ------------------- layer-2 softmax+gather, fp16 gather -------------------
__global__ void k_agg2() {
    int gw = (blockIdx.x * blockDim.x + threadIdx.x) >> 5;
    int lane = threadIdx.x & 31;
    if (gw >= NN) return;
    int beg = g_off[gw], end = g_off[gw + 1];
    float ad = g_ad2[gw];

    float m = -1e30f, den = 0.f;
    for (int i = beg + lane; i < end; i += 32) {
        float v = lrelu(g_as2[g_csr[i]] + ad);
        float mn = fmaxf(m, v);
        den = den * __expf(m - mn) + __expf(v - mn);
        m = mn;
    }
    #pragma unroll
    for (int o = 16; o; o >>= 1) {
        float mo = __shfl_xor_sync(0xffffffffu, m, o);
        float dd = __shfl_xor_sync(0xffffffffu, den, o);
        float mn = fmaxf(m, mo);
        den = den * __expf(m - mn) + dd * __expf(mo - mn);
        m = mn;
    }
    float inv = 1.f / (den + 1e-16f);

    float4 acc = make_float4(0.f, 0.f, 0.f, 0.f);
    const uint2* __restrict__ h2h = (const uint2*)g_h2h;
    for (int i = beg; i < end; i++) {
        int s = g_csr[i];
        float c = __expf(lrelu(g_as2[s] + ad) - m) * inv;
        uint2 raw = h2h[(size_t)s * 32 + lane];
        float2 f0 = __half22float2(*(__half2*)&raw.x);
        float2 f1 = __half22float2(*(__half2*)&raw.y);
        acc.x += f0.x * c; acc.y += f0.y * c; acc.z += f1.x * c; acc.w += f1.y * c;
    }
    ((float4*)(g_out2 + (size_t)gw * OUT_DIM))[lane] = acc;
}

// ------------------- batchnorm -------------------
#define SROWS 80
__global__ void k_stats1() {
    int c = threadIdx.x;
    int r0 = blockIdx.x * SROWS;
    int rend = r0 + SROWS; if (rend > NN) rend = NN;
    float s = 0.f, s2 = 0.f;
    for (int r = r0; r < rend; r++) {
        float v = g_out1[(size_t)r * HID + c];
        s += v; s2 += v * v;
    }
    atomicAdd(&g_sum[c], s); atomicAdd(&g_sqs[c], s2);
}
__global__ void k_apply1(const float* __restrict__ gamma, const float* __restrict__ beta) {
    int i = blockIdx.x * blockDim.x + threadIdx.x;
    if (i < NN) g_as2[i] = 0.f;                       // zero alpha2 accumulators
    else if (i < 2 * NN) g_ad2[i - NN] = 0.f;
    if (i >= NN * HID) return;
    int c = i & (HID - 1);
    float mean = g_sum[c] * (1.f / NN);
    float var = g_sqs[c] * (1.f / NN) - mean * mean;
    float v = (g_out1[i] - mean) * rsqrtf(var + 1e-5f) * gamma[c] + beta[c];
    g_out1[i] = v > 0.f ? v : (__expf(v) - 1.f);      // ELU
}
__global__ void k_stats2() {
    int c = threadIdx.x;
    int r0 = blockIdx.x * SROWS;
    int rend = r0 + SROWS; if (rend > NN) rend = NN;
    float s = 0.f, s2 = 0.f;
    for (int r = r0; r < rend; r++) {
        float v = g_out2[(size_t)r * OUT_DIM + c];
        s += v; s2 += v * v;
    }
    atomicAdd(&g_sum[c], s); atomicAdd(&g_sqs[c], s2);
}
__global__ void k_apply2(const float* __restrict__ gamma, const float* __restrict__ beta,
                         float* __restrict__ out) {
    int i = blockIdx.x * blockDim.x + threadIdx.x;
    if (i < NN) g_cnt[i] = 0;                 // re-arm counts for next call
    if (i >= NN * OUT_DIM) return;
    int c = i & (OUT_DIM - 1);
    float mean = g_sum[c] * (1.f / NN);
    float var = g_sqs[c] * (1.f / NN) - mean * mean;
    out[i] = (g_out2[i] - mean) * rsqrtf(var + 1e-5f) * gamma[c] + beta[c];
}

// ------------------- launch -------------------
extern "C" void kernel_launch(void* const* d_in, const int* in_sizes, int n_in,
                              void* d_out, int out_size) {
    const float* x     = (const float*)d_in[0];
    const void*  ei    = d_in[1];
    const float* W1    = (const float*)d_in[2];
    const float* asrc1 = (const float*)d_in[3];
    const float* adst1 = (const float*)d_in[4];
    const float* g1    = (const float*)d_in[6];
    const float* b1    = (const float*)d_in[7];
    const float* W2    = (const float*)d_in[8];
    const float* asrc2 = (const float*)d_in[9];
    const float* adst2 = (const float*)d_in[10];
    const float* g2    = (const float*)d_in[12];
    const float* b2    = (const float*)d_in[13];
    float* out = (float*)d_out;

    const int T = 256;
    const int EB = (ETOT + T - 1) / T;
    const int SB = (NN + SROWS - 1) / SROWS;

    k_decode<<<EB, T>>>(ei);                                        // + count + zero BN
    k_gemm1<<<dim3(HID / 64, (NN + 127) / 128), T>>>(x, W1, asrc1, adst1);  // 3xTF32 + alpha1 + fp16 copy
    k_scan<<<1, 256>>>();
    k_fill<<<EB, T>>>();
    k_agg1<<<(NN * 64 + T - 1) / T, T>>>();                          // fp16 gather
    k_stats1<<<SB, 256>>>();
    k_apply1<<<(NN * HID + T - 1) / T, T>>>(g1, b1);                 // + zero alpha2 accums
    k_gemm2<<<dim3(OUT_DIM / 64, (NN + 127) / 128), T>>>(W2, asrc2, adst2); // + alpha2 + zero BN + fp16 only
    k_agg2<<<(NN * 32 + T - 1) / T, T>>>();                          // fp16 gather
    k_stats2<<<SB, 128>>>();
    k_apply2<<<(NN * OUT_DIM + T - 1) / T, T>>>(g2, b2, out);        // + re-zero g_cnt
}